// round 3
// baseline (speedup 1.0000x reference)
#include <cuda_runtime.h>

// FwFM forward on GB300 — R3: row-parity split of the pair triangle across
// two warps per sample group to double chip occupancy (grid 512 -> 1024).
//
// Layout: block = 4 warps = 128 threads.
//   warp w: samples [ (w>>1)*4 .. +3 ], row parity g = w&1 (warp-uniform).
//   within warp: sub = lane>>3 (sample 0..3), d = lane&7 (dims 2d,2d+1 packed).
// Each warp computes its parity's rows of  sum_{i<j} w_p <e_i,e_j>  using
// packed fma.rn.f32x2 with 4 independent accumulators per row; the two
// parity partials combine through shared memory.

#define FIELDS 39
#define EDIM 16
#define CROSS 741            // 39*38/2
#define BATCH 8192
#define SAMPLES_PER_BLOCK 8
#define THREADS 128

typedef unsigned long long ull;

__device__ __forceinline__ ull pk_zero() {
    ull v;
    asm("mov.b64 %0, {%1, %1};" : "=l"(v) : "f"(0.0f));
    return v;
}
__device__ __forceinline__ ull pk_fma(ull a, ull b, ull c) {
    ull r;
    asm("fma.rn.f32x2 %0, %1, %2, %3;" : "=l"(r) : "l"(a), "l"(b), "l"(c));
    return r;
}
__device__ __forceinline__ ull pk_add(ull a, ull b) {
    ull r;
    asm("add.rn.f32x2 %0, %1, %2;" : "=l"(r) : "l"(a), "l"(b));
    return r;
}

// Pair index base for row i: offset(i) = 38*i - i*(i-1)/2, p = offset + (j-i-1).
// All i are compile-time constants after unrolling.
template<int START>
__device__ __forceinline__ ull rows_partial(const ull* __restrict__ x,
                                            const ull* __restrict__ w2)
{
    ull acc = pk_zero();
#pragma unroll
    for (int i = START; i < FIELDS - 1; i += 2) {
        const int rowbase = 38 * i - (i * (i - 1)) / 2 - (i + 1);
        ull t0 = pk_zero(), t1 = pk_zero(), t2 = pk_zero(), t3 = pk_zero();
#pragma unroll
        for (int j = i + 1; j < FIELDS; j++) {
            const ull wx = w2[rowbase + j];
            switch ((j - i - 1) & 3) {
                case 0: t0 = pk_fma(wx, x[j], t0); break;
                case 1: t1 = pk_fma(wx, x[j], t1); break;
                case 2: t2 = pk_fma(wx, x[j], t2); break;
                default: t3 = pk_fma(wx, x[j], t3); break;
            }
        }
        const ull ts = pk_add(pk_add(t0, t1), pk_add(t2, t3));
        acc = pk_fma(x[i], ts, acc);
    }
    return acc;
}

__global__ __launch_bounds__(THREADS)
void fwfm_kernel(const int* __restrict__ inputs,
                 const float* __restrict__ emb,
                 const float* __restrict__ fw,
                 const float* __restrict__ lw,
                 const float* __restrict__ bias,
                 float* __restrict__ out)
{
    __shared__ ull w2[CROSS];                         // {w,w} splatted pair weights
    __shared__ int idx_sh[SAMPLES_PER_BLOCK * FIELDS];
    __shared__ float partial[SAMPLES_PER_BLOCK][2];

    const int tid = threadIdx.x;

    for (int p = tid; p < CROSS; p += THREADS) {
        float w = fw[p];
        ull v;
        asm("mov.b64 %0, {%1, %1};" : "=l"(v) : "f"(w));
        w2[p] = v;
    }
    const int base = blockIdx.x * SAMPLES_PER_BLOCK * FIELDS;
    for (int k = tid; k < SAMPLES_PER_BLOCK * FIELDS; k += THREADS)
        idx_sh[k] = inputs[base + k];
    __syncthreads();

    const int warp = tid >> 5;
    const int lane = tid & 31;
    const int g    = warp & 1;        // row parity handled by this warp
    const int sub  = lane >> 3;       // sample within group (0..3)
    const int d    = lane & 7;        // dim-pair (dims 2d, 2d+1)
    const int s_local = (warp >> 1) * 4 + sub;
    const int* my_idx = &idx_sh[s_local * FIELDS];

    // Gather embeddings: 8 lanes of a sample cover one 64B row per field.
    ull x[FIELDS];
#pragma unroll
    for (int f = 0; f < FIELDS; f++) {
        const int gi = my_idx[f];
        x[f] = *reinterpret_cast<const ull*>(emb + (size_t)gi * EDIM + 2 * d);
    }

    // First order split between the two parity warps (warp-uniform bounds).
    float lin = 0.f;
    if (g == 0) {
        lin += lw[my_idx[d]];
        lin += lw[my_idx[d + 16]];
        if (d < 7) lin += lw[my_idx[d + 32]];
    } else {
        lin += lw[my_idx[d + 8]];
        lin += lw[my_idx[d + 24]];
    }

    // Second order: this warp's parity rows only (warp-uniform branch).
    ull acc = (g == 0) ? rows_partial<0>(x, w2) : rows_partial<1>(x, w2);

    float lo, hi;
    asm("mov.b64 {%0, %1}, %2;" : "=f"(lo), "=f"(hi) : "l"(acc));
    float v = lo + hi + lin;

    // Reduce across the 8 lanes of this sample's dim group.
    v += __shfl_xor_sync(0xffffffffu, v, 4);
    v += __shfl_xor_sync(0xffffffffu, v, 2);
    v += __shfl_xor_sync(0xffffffffu, v, 1);

    if (d == 0) partial[s_local][g] = v;
    __syncthreads();

    if (tid < SAMPLES_PER_BLOCK) {
        out[blockIdx.x * SAMPLES_PER_BLOCK + tid] =
            partial[tid][0] + partial[tid][1] + bias[0];
    }
}

extern "C" void kernel_launch(void* const* d_in, const int* in_sizes, int n_in,
                              void* d_out, int out_size)
{
    const int*   inputs = (const int*)d_in[0];
    const float* emb    = (const float*)d_in[1];
    const float* fw     = (const float*)d_in[2];
    const float* lw     = (const float*)d_in[3];
    const float* bias   = (const float*)d_in[4];
    float*       out    = (float*)d_out;

    fwfm_kernel<<<BATCH / SAMPLES_PER_BLOCK, THREADS>>>(inputs, emb, fw, lw, bias, out);
}

// round 4
// speedup vs baseline: 1.6815x; 1.6815x over previous
#include <cuda_runtime.h>

// FwFM forward on GB300 — R4: back to R2 structure (1 warp owns 4 samples,
// 8 lanes/sample, packed f32x2), plus:
//  * 64-thread blocks (2 warps, 8 samples) -> grid 1024, 7/6 blocks/SM mix
//    instead of 4/3 (kills the ~15% tail imbalance of grid 512).
//  * pair weights stored row-padded-to-4 in smem as floats; inner loop loads
//    them as float4 (LDS.128, one broadcast per 4 pairs) and splats to {w,w}
//    in registers on the ALU pipe. Zero padding makes every row an exact
//    number of quads (x[39..41] zeroed so pad terms contribute 0).

#define FIELDS 39
#define EDIM 16
#define BATCH 8192
#define SAMPLES_PER_BLOCK 8
#define THREADS 64
#define XPAD 42              // fields rounded up so padded quads stay in range
#define W2PAD 864            // >= sum of padded row lengths (~798)

typedef unsigned long long ull;

__device__ __forceinline__ ull pk_zero() {
    ull v;
    asm("mov.b64 %0, {%1, %1};" : "=l"(v) : "f"(0.0f));
    return v;
}
__device__ __forceinline__ ull pk_splat(float w) {
    ull v;
    asm("mov.b64 %0, {%1, %1};" : "=l"(v) : "f"(w));
    return v;
}
__device__ __forceinline__ ull pk_fma(ull a, ull b, ull c) {
    ull r;
    asm("fma.rn.f32x2 %0, %1, %2, %3;" : "=l"(r) : "l"(a), "l"(b), "l"(c));
    return r;
}
__device__ __forceinline__ ull pk_add(ull a, ull b) {
    ull r;
    asm("add.rn.f32x2 %0, %1, %2;" : "=l"(r) : "l"(a), "l"(b));
    return r;
}

__global__ __launch_bounds__(THREADS, 7)
void fwfm_kernel(const int* __restrict__ inputs,
                 const float* __restrict__ emb,
                 const float* __restrict__ fw,
                 const float* __restrict__ lw,
                 const float* __restrict__ bias,
                 float* __restrict__ out)
{
    __shared__ __align__(16) float w2[W2PAD];   // row-padded pair weights
    __shared__ int idx_sh[SAMPLES_PER_BLOCK * FIELDS];

    const int tid = threadIdx.x;

    // Zero the padded weight array (pads must be 0).
    for (int k = tid; k < W2PAD; k += THREADS)
        w2[k] = 0.0f;
    __syncthreads();

    // Fill: row i has len = 38-i source weights starting at orig offset os(i),
    // placed at padded offset ps(i) (rows padded to multiples of 4).
    {
        int os = 0, ps = 0;
        for (int i = 0; i < FIELDS - 1; i++) {
            const int len = FIELDS - 1 - i;
            for (int k = tid; k < len; k += THREADS)
                w2[ps + k] = fw[os + k];
            os += len;
            ps += (len + 3) & ~3;
        }
    }
    const int base = blockIdx.x * SAMPLES_PER_BLOCK * FIELDS;
    for (int k = tid; k < SAMPLES_PER_BLOCK * FIELDS; k += THREADS)
        idx_sh[k] = inputs[base + k];
    __syncthreads();

    const int warp = tid >> 5;
    const int lane = tid & 31;
    const int sub  = lane >> 3;       // sample within warp (0..3)
    const int d    = lane & 7;        // dim-pair (dims 2d, 2d+1)
    const int s_local = warp * 4 + sub;
    const int sample  = blockIdx.x * SAMPLES_PER_BLOCK + s_local;
    const int* my_idx = &idx_sh[s_local * FIELDS];

    // Gather: lane d loads dims [2d,2d+1] of each field; 8 lanes cover the
    // 64B row -> one L2 line per field. 39 independent LDG.64 (high MLP).
    ull x[XPAD];
#pragma unroll
    for (int f = 0; f < FIELDS; f++) {
        const int g = my_idx[f];
        x[f] = *reinterpret_cast<const ull*>(emb + (size_t)g * EDIM + 2 * d);
    }
#pragma unroll
    for (int f = FIELDS; f < XPAD; f++)
        x[f] = pk_zero();             // pad terms must be exactly 0

    // First-order partial: lane d covers fields f == d (mod 8).
    float lin = 0.f;
#pragma unroll
    for (int f = d; f < FIELDS; f += 8)
        lin += lw[my_idx[f]];

    // Second order: row i -> t = sum_j w * x[j], acc += x[i]*t.
    // Weights consumed 4-at-a-time via one float4 broadcast LDS.128.
    ull acc = pk_zero();
    {
        int ps = 0;
#pragma unroll
        for (int i = 0; i < FIELDS - 1; i++) {
            const int len  = FIELDS - 1 - i;
            const int nq   = (len + 3) >> 2;          // padded quads
            ull t0 = pk_zero(), t1 = pk_zero(), t2 = pk_zero(), t3 = pk_zero();
#pragma unroll
            for (int q = 0; q < nq; q++) {
                const float4 wq = *reinterpret_cast<const float4*>(&w2[ps + 4 * q]);
                const int j0 = i + 1 + 4 * q;
                t0 = pk_fma(pk_splat(wq.x), x[j0 + 0], t0);
                t1 = pk_fma(pk_splat(wq.y), x[j0 + 1], t1);
                t2 = pk_fma(pk_splat(wq.z), x[j0 + 2], t2);
                t3 = pk_fma(pk_splat(wq.w), x[j0 + 3], t3);
            }
            const ull ts = pk_add(pk_add(t0, t1), pk_add(t2, t3));
            acc = pk_fma(x[i], ts, acc);
            ps += nq << 2;
        }
    }

    float lo, hi;
    asm("mov.b64 {%0, %1}, %2;" : "=f"(lo), "=f"(hi) : "l"(acc));
    float v = lo + hi + lin;

    // Reduce across the 8 lanes of this sample (xor 4,2,1 stays in-group).
    v += __shfl_xor_sync(0xffffffffu, v, 4);
    v += __shfl_xor_sync(0xffffffffu, v, 2);
    v += __shfl_xor_sync(0xffffffffu, v, 1);

    if (d == 0)
        out[sample] = v + bias[0];
}

extern "C" void kernel_launch(void* const* d_in, const int* in_sizes, int n_in,
                              void* d_out, int out_size)
{
    const int*   inputs = (const int*)d_in[0];
    const float* emb    = (const float*)d_in[1];
    const float* fw     = (const float*)d_in[2];
    const float* lw     = (const float*)d_in[3];
    const float* bias   = (const float*)d_in[4];
    float*       out    = (float*)d_out;

    fwfm_kernel<<<BATCH / SAMPLES_PER_BLOCK, THREADS>>>(inputs, emb, fw, lw, bias, out);
}